// round 12
// baseline (speedup 1.0000x reference)
#include <cuda_runtime.h>
#include <cuda_fp16.h>
#include <cstdint>

// ---------------------------------------------------------------------------
// InstantNGP round 12: R11 (M=32 tile, uint4 weight frags) + interleaved
// dual-subtile gather: both 16-point halves per level -> 8 LDG.128 in flight.
// 256 thr/CTA, 2 CTAs/SM.
// ---------------------------------------------------------------------------

constexpr int THREADS = 256;
constexpr int WARPS = THREADS / 32;
constexpr unsigned TMASK = 524287u;      // T = 2^19 - 1
constexpr float SCALE = 1024.0f;         // density-MLP domain scale (2^10)
constexpr float INV_SCALE = 1.0f / 1024.0f;
constexpr int ST = 36;                   // stage row stride in halves (72B)

__device__ __forceinline__ void mma16816(float d[4], const uint32_t a[4],
                                         uint32_t b0, uint32_t b1) {
    asm volatile("mma.sync.aligned.m16n8k16.row.col.f32.f16.f16.f32 "
        "{%0,%1,%2,%3}, {%4,%5,%6,%7}, {%8,%9}, {%0,%1,%2,%3};"
        : "+f"(d[0]), "+f"(d[1]), "+f"(d[2]), "+f"(d[3])
        : "r"(a[0]), "r"(a[1]), "r"(a[2]), "r"(a[3]), "r"(b0), "r"(b1));
}

__device__ __forceinline__ uint32_t pack_h2(float x, float y) {
    __half2 h = __floats2half2_rn(x, y);
    return *(uint32_t*)&h;
}
__device__ __forceinline__ uint32_t pack_relu(float x, float y) {
    return pack_h2(fmaxf(x, 0.0f), fmaxf(y, 0.0f));
}

// M=32 layer: one uint4 weight load feeds 4 MMAs (2 n-tiles x 2 m-tiles).
template<int KT, int NT>   // NT even
__device__ __forceinline__ void run_layer32(const uint4* __restrict__ F,
                                            const uint32_t A[2][4][4],
                                            float D[2][8][4], int lane) {
    #pragma unroll
    for (int m = 0; m < 2; m++)
        #pragma unroll
        for (int nt = 0; nt < NT; nt++)
            #pragma unroll
            for (int i = 0; i < 4; i++) D[m][nt][i] = 0.0f;
    #pragma unroll
    for (int kt = 0; kt < KT; kt++)
        #pragma unroll
        for (int ntp = 0; ntp < NT / 2; ntp++) {
            uint4 B = F[(kt * (NT / 2) + ntp) * 32 + lane];
            mma16816(D[0][2 * ntp],     A[0][kt], B.x, B.y);
            mma16816(D[1][2 * ntp],     A[1][kt], B.x, B.y);
            mma16816(D[0][2 * ntp + 1], A[0][kt], B.z, B.w);
            mma16816(D[1][2 * ntp + 1], A[1][kt], B.z, B.w);
        }
}

// final 64->3 layer (one n-tile): uint2 frags
__device__ __forceinline__ void run_layer32_n8(const uint2* __restrict__ F,
                                               const uint32_t A[2][4][4],
                                               float D[2][8][4], int lane) {
    #pragma unroll
    for (int m = 0; m < 2; m++)
        #pragma unroll
        for (int i = 0; i < 4; i++) D[m][0][i] = 0.0f;
    #pragma unroll
    for (int kt = 0; kt < 4; kt++) {
        uint2 B = F[kt * 32 + lane];
        mma16816(D[0][0], A[0][kt], B.x, B.y);
        mma16816(D[1][0], A[1][kt], B.x, B.y);
    }
}

// fp32 D (+bias, relu) -> f16 A fragments of next layer, fully in registers.
template<int NT>
__device__ __forceinline__ void convert_relu(const float D[2][8][4],
                                             const float* __restrict__ bias,
                                             uint32_t A[2][4][4], int lane) {
    const int c = (lane & 3) * 2;
    #pragma unroll
    for (int kt = 0; kt < NT / 2; kt++) {
        const int j = 2 * kt;
        float b00 = bias[8 * j + c],     b01 = bias[8 * j + c + 1];
        float b10 = bias[8 * j + 8 + c], b11 = bias[8 * j + 8 + c + 1];
        #pragma unroll
        for (int m = 0; m < 2; m++) {
            A[m][kt][0] = pack_relu(D[m][j][0] + b00,     D[m][j][1] + b01);
            A[m][kt][1] = pack_relu(D[m][j][2] + b00,     D[m][j][3] + b01);
            A[m][kt][2] = pack_relu(D[m][j + 1][0] + b10, D[m][j + 1][1] + b11);
            A[m][kt][3] = pack_relu(D[m][j + 1][2] + b10, D[m][j + 1][3] + b11);
        }
    }
}

// load A fragments (2 m-tiles x 2 k-tiles) from per-warp 32-row stage
__device__ __forceinline__ void load_A2(const __half* __restrict__ st,
                                        uint32_t A[2][4][4], int lane) {
    const int r = lane >> 2, c = (lane & 3) * 2;
    #pragma unroll
    for (int m = 0; m < 2; m++)
        #pragma unroll
        for (int kt = 0; kt < 2; kt++) {
            int row = r + 16 * m, col = c + 16 * kt;
            A[m][kt][0] = *(const uint32_t*)(st + row * ST + col);
            A[m][kt][1] = *(const uint32_t*)(st + (row + 8) * ST + col);
            A[m][kt][2] = *(const uint32_t*)(st + row * ST + col + 8);
            A[m][kt][3] = *(const uint32_t*)(st + (row + 8) * ST + col + 8);
        }
}

// fill vectorized frag groups (NT even)
__device__ __forceinline__ void fill_frags_v4(uint4* frag, const float* __restrict__ W,
                                              int K, int Nout, int KT, int NT, int tid) {
    const int total = KT * (NT / 2) * 32;
    for (int v = tid; v < total; v += THREADS) {
        int lane = v & 31, g = v >> 5;
        int kt = g / (NT / 2), ntp = g % (NT / 2);
        uint32_t words[4];
        #pragma unroll
        for (int j = 0; j < 4; j++) {
            int nt = ntp * 2 + (j >> 1), reg = j & 1;
            int k = kt * 16 + (lane & 3) * 2 + reg * 8;
            int n = nt * 8 + (lane >> 2);
            float w0 = (k < K && n < Nout) ? W[k * Nout + n] : 0.0f;
            float w1 = (k + 1 < K && n < Nout) ? W[(k + 1) * Nout + n] : 0.0f;
            words[j] = pack_h2(w0, w1);
        }
        frag[v] = make_uint4(words[0], words[1], words[2], words[3]);
    }
}

__device__ __forceinline__ void fill_frags_v2(uint2* frag, const float* __restrict__ W,
                                              int K, int Nout, int tid) {
    for (int v = tid; v < 4 * 32; v += THREADS) {
        int lane = v & 31, kt = v >> 5;
        uint32_t words[2];
        #pragma unroll
        for (int reg = 0; reg < 2; reg++) {
            int k = kt * 16 + (lane & 3) * 2 + reg * 8;
            int n = lane >> 2;
            float w0 = (k < K && n < Nout) ? W[k * Nout + n] : 0.0f;
            float w1 = (k + 1 < K && n < Nout) ? W[(k + 1) * Nout + n] : 0.0f;
            words[reg] = pack_h2(w0, w1);
        }
        frag[v] = make_uint2(words[0], words[1]);
    }
}

// per-lane corner indices (with level offset) + weights for one level
__device__ __forceinline__ void hash_level(int l, float res, float Px, float Py, float Pz,
                                           int half, unsigned idx[4], float w[4]) {
    float px = Px * res, py = Py * res, pz = Pz * res;
    float fx = floorf(px), fy = floorf(py), fz = floorf(pz);
    float fracx = px - fx;
    float wxh = half ? fracx : (1.0f - fracx);
    float wy1 = py - fy, wy0 = 1.0f - wy1;
    float wz1 = pz - fz, wz0 = 1.0f - wz1;
    unsigned ix = (unsigned)fx, iy = (unsigned)fy, iz = (unsigned)fz;
    unsigned hxh = ix + (unsigned)half;
    unsigned hy0 = iy * 2654435761u, hy1 = (iy + 1u) * 2654435761u;
    unsigned hz0 = iz * 805459861u,  hz1 = (iz + 1u) * 805459861u;
    const unsigned base = (unsigned)l << 19;
    idx[0] = ((hxh ^ hy0 ^ hz0) & TMASK) + base;  w[0] = wxh * wy0 * wz0;
    idx[1] = ((hxh ^ hy0 ^ hz1) & TMASK) + base;  w[1] = wxh * wy0 * wz1;
    idx[2] = ((hxh ^ hy1 ^ hz0) & TMASK) + base;  w[2] = wxh * wy1 * wz0;
    idx[3] = ((hxh ^ hy1 ^ hz1) & TMASK) + base;  w[3] = wxh * wy1 * wz1;
}

__global__ __launch_bounds__(THREADS, 2)
void ngp_mma_kernel(const float* __restrict__ pts,
                    const float* __restrict__ views,
                    const float* __restrict__ tables,
                    const float* __restrict__ W1, const float* __restrict__ b1,
                    const float* __restrict__ W2, const float* __restrict__ b2,
                    const float* __restrict__ W3, const float* __restrict__ b3,
                    const float* __restrict__ W4, const float* __restrict__ b4,
                    const float* __restrict__ W5, const float* __restrict__ b5,
                    const float* __restrict__ W6, const float* __restrict__ b6,
                    const float* __restrict__ W7, const float* __restrict__ b7,
                    float* __restrict__ out, int N, int n_wtiles) {
    __shared__ uint4 sF1[256], sF2[512], sF3[128], sF4[256], sF5[512], sF6[512];
    __shared__ uint2 sF7[128];
    __shared__ float sB1[64], sB2[64], sB3[16], sB4[64], sB5[64], sB6[64], sB7[4];
    __shared__ __half sStage[WARPS][32 * ST];

    const int tid = threadIdx.x;
    fill_frags_v4(sF1, W1, 32, 64, 2, 8, tid);
    fill_frags_v4(sF2, W2, 64, 64, 4, 8, tid);
    fill_frags_v4(sF3, W3, 64, 16, 4, 2, tid);
    fill_frags_v4(sF4, W4, 31, 64, 2, 8, tid);
    fill_frags_v4(sF5, W5, 64, 64, 4, 8, tid);
    fill_frags_v4(sF6, W6, 64, 64, 4, 8, tid);
    fill_frags_v2(sF7, W7, 64, 3, tid);
    if (tid < 64) {
        sB1[tid] = b1[tid] * SCALE;
        sB2[tid] = b2[tid] * SCALE;
        sB4[tid] = b4[tid];
        sB5[tid] = b5[tid];
        sB6[tid] = b6[tid];
    }
    if (tid < 16) sB3[tid] = b3[tid] * SCALE;
    if (tid < 4)  sB7[tid] = (tid < 3) ? b7[tid] : 0.0f;
    __syncthreads();

    const int lane = tid & 31, wid = tid >> 5;
    __half* st = sStage[wid];
    const int r = lane >> 2, cbase = (lane & 3) * 2;
    const int pt = lane & 15, half = lane >> 4;

    // level resolutions: 16 * 2^(6l/7) (correctness-proven form)
    float resl[8];
    #pragma unroll
    for (int l = 0; l < 8; l++)
        resl[l] = 16.0f * exp2f((float)l * (6.0f / 7.0f));

    const float4* __restrict__ tabs = (const float4*)tables;

    for (int t = blockIdx.x * WARPS + wid; t < n_wtiles; t += gridDim.x * WARPS) {
        const int p0 = t * 32;

        // ---- interleaved dual-subtile gather: per level, compute indices for
        //      both 16-point halves, issue all 8 LDG.128, then weight both ----
        {
            const int pA = p0 + pt,      pB = p0 + 16 + pt;
            const int ppA = pA < N ? pA : N - 1;
            const int ppB = pB < N ? pB : N - 1;
            const float PAx = pts[3 * ppA], PAy = pts[3 * ppA + 1], PAz = pts[3 * ppA + 2];
            const float PBx = pts[3 * ppB], PBy = pts[3 * ppB + 1], PBz = pts[3 * ppB + 2];

            #pragma unroll 1
            for (int l = 0; l < 8; l++) {
                unsigned iA[4], iB[4];
                float wA[4], wB[4];
                hash_level(l, resl[l], PAx, PAy, PAz, half, iA, wA);
                hash_level(l, resl[l], PBx, PBy, PBz, half, iB, wB);
                float4 fA0 = __ldg(tabs + iA[0]);
                float4 fA1 = __ldg(tabs + iA[1]);
                float4 fA2 = __ldg(tabs + iA[2]);
                float4 fA3 = __ldg(tabs + iA[3]);
                float4 fB0 = __ldg(tabs + iB[0]);
                float4 fB1 = __ldg(tabs + iB[1]);
                float4 fB2 = __ldg(tabs + iB[2]);
                float4 fB3 = __ldg(tabs + iB[3]);

                float a0 = wA[0]*fA0.x + wA[1]*fA1.x + wA[2]*fA2.x + wA[3]*fA3.x;
                float a1 = wA[0]*fA0.y + wA[1]*fA1.y + wA[2]*fA2.y + wA[3]*fA3.y;
                float a2 = wA[0]*fA0.z + wA[1]*fA1.z + wA[2]*fA2.z + wA[3]*fA3.z;
                float a3 = wA[0]*fA0.w + wA[1]*fA1.w + wA[2]*fA2.w + wA[3]*fA3.w;
                a0 += __shfl_xor_sync(0xffffffffu, a0, 16);
                a1 += __shfl_xor_sync(0xffffffffu, a1, 16);
                a2 += __shfl_xor_sync(0xffffffffu, a2, 16);
                a3 += __shfl_xor_sync(0xffffffffu, a3, 16);

                float b0v = wB[0]*fB0.x + wB[1]*fB1.x + wB[2]*fB2.x + wB[3]*fB3.x;
                float b1v = wB[0]*fB0.y + wB[1]*fB1.y + wB[2]*fB2.y + wB[3]*fB3.y;
                float b2v = wB[0]*fB0.z + wB[1]*fB1.z + wB[2]*fB2.z + wB[3]*fB3.z;
                float b3v = wB[0]*fB0.w + wB[1]*fB1.w + wB[2]*fB2.w + wB[3]*fB3.w;
                b0v += __shfl_xor_sync(0xffffffffu, b0v, 16);
                b1v += __shfl_xor_sync(0xffffffffu, b1v, 16);
                b2v += __shfl_xor_sync(0xffffffffu, b2v, 16);
                b3v += __shfl_xor_sync(0xffffffffu, b3v, 16);

                if (half == 0) {
                    uint2 vA = make_uint2(pack_h2(a0 * SCALE, a1 * SCALE),
                                          pack_h2(a2 * SCALE, a3 * SCALE));
                    *(uint2*)(st + pt * ST + 4 * l) = vA;
                    uint2 vB = make_uint2(pack_h2(b0v * SCALE, b1v * SCALE),
                                          pack_h2(b2v * SCALE, b3v * SCALE));
                    *(uint2*)(st + (16 + pt) * ST + 4 * l) = vB;
                }
            }
        }
        __syncwarp();

        uint32_t A[2][4][4];
        float D[2][8][4];

        load_A2(st, A, lane);
        run_layer32<2, 8>(sF1, A, D, lane);
        convert_relu<8>(D, sB1, A, lane);
        run_layer32<4, 8>(sF2, A, D, lane);
        convert_relu<8>(D, sB2, A, lane);
        run_layer32<4, 2>(sF3, A, D, lane);

        // ---------- density out + stage x16[1:16] ----------
        __syncwarp();   // all lanes done reading stage (L1 input) before overwrite
        #pragma unroll
        for (int m = 0; m < 2; m++) {
            const int row0 = r + 16 * m;
            if ((lane & 3) == 0) {
                float v0 = (D[m][0][0] + sB3[0]) * INV_SCALE;
                float v2 = (D[m][0][2] + sB3[0]) * INV_SCALE;
                int pt0 = p0 + row0, pt1 = p0 + row0 + 8;
                if (pt0 < N) out[3 * N + pt0] = fmaxf(v0, 0.0f);
                if (pt1 < N) out[3 * N + pt1] = fmaxf(v2, 0.0f);
            }
            #pragma unroll
            for (int nt = 0; nt < 2; nt++) {
                #pragma unroll
                for (int i = 0; i < 2; i++) {
                    int g = 8 * nt + cbase + i;
                    if (g >= 1) {
                        float bb = sB3[g];
                        st[row0 * ST + (g - 1)]       = __float2half((D[m][nt][i]     + bb) * INV_SCALE);
                        st[(row0 + 8) * ST + (g - 1)] = __float2half((D[m][nt][2 + i] + bb) * INV_SCALE);
                    }
                }
            }
        }

        // ---------- SH(view) -> stage cols 15..30, col31 = 0 (two passes) ----
        #pragma unroll 1
        for (int u = 0; u < 2; u++) {
            if (half == 0) {
                const int prow = 16 * u + pt;
                const int p = p0 + prow;
                const int pp = p < N ? p : N - 1;
                const float vx = views[3 * pp], vy = views[3 * pp + 1], vz = views[3 * pp + 2];
                float inv = rsqrtf(vx * vx + vy * vy + vz * vz);
                float x = vx * inv, y = vy * inv, z = vz * inv;
                float xx = x * x, yy = y * y, zz = z * z;
                __half* row = st + prow * ST;
                row[15] = __float2half(0.28209479177387814f);
                row[16] = __float2half(-0.48860251190291987f * y);
                row[17] = __float2half(0.48860251190291987f * z);
                row[18] = __float2half(-0.48860251190291987f * x);
                row[19] = __float2half(1.0925484305920792f * x * y);
                row[20] = __float2half(-1.0925484305920792f * y * z);
                row[21] = __float2half(0.94617469575755997f * zz - 0.31539156525252005f);
                row[22] = __float2half(-1.0925484305920792f * x * z);
                row[23] = __float2half(0.54627421529603959f * (xx - yy));
                row[24] = __float2half(-0.59004358992664352f * y * (3.0f * xx - yy));
                row[25] = __float2half(2.8906114426405538f * x * y * z);
                row[26] = __float2half(-0.45704579946446572f * y * (4.0f * zz - xx - yy));
                row[27] = __float2half(0.37317633259011546f * z * (2.0f * zz - 3.0f * xx - 3.0f * yy));
                row[28] = __float2half(-0.45704579946446572f * x * (4.0f * zz - xx - yy));
                row[29] = __float2half(1.4453057213202769f * z * (xx - yy));
                row[30] = __float2half(-0.59004358992664352f * x * (xx - 3.0f * yy));
                row[31] = __float2half(0.0f);
            }
        }
        __syncwarp();

        load_A2(st, A, lane);
        run_layer32<2, 8>(sF4, A, D, lane);
        convert_relu<8>(D, sB4, A, lane);
        run_layer32<4, 8>(sF5, A, D, lane);
        convert_relu<8>(D, sB5, A, lane);
        run_layer32<4, 8>(sF6, A, D, lane);
        convert_relu<8>(D, sB6, A, lane);
        run_layer32_n8(sF7, A, D, lane);

        // ---------- sigmoid color out (cols 0..2 of D ntile 0) ----------
        #pragma unroll
        for (int m = 0; m < 2; m++) {
            #pragma unroll
            for (int i = 0; i < 2; i++) {
                int col = cbase + i;
                if (col < 3) {
                    int pt0 = p0 + r + 16 * m, pt1 = pt0 + 8;
                    float o0 = D[m][0][i] + sB7[col];
                    float o1 = D[m][0][2 + i] + sB7[col];
                    if (pt0 < N) out[3 * pt0 + col] = 1.0f / (1.0f + __expf(-o0));
                    if (pt1 < N) out[3 * pt1 + col] = 1.0f / (1.0f + __expf(-o1));
                }
            }
        }
        __syncwarp();  // stage reuse safety for next iteration
    }
}

extern "C" void kernel_launch(void* const* d_in, const int* in_sizes, int n_in,
                              void* d_out, int out_size) {
    const float* pts    = (const float*)d_in[0];
    const float* views  = (const float*)d_in[1];
    const float* tables = (const float*)d_in[2];
    const float* W1 = (const float*)d_in[3];  const float* b1 = (const float*)d_in[4];
    const float* W2 = (const float*)d_in[5];  const float* b2 = (const float*)d_in[6];
    const float* W3 = (const float*)d_in[7];  const float* b3 = (const float*)d_in[8];
    const float* W4 = (const float*)d_in[9];  const float* b4 = (const float*)d_in[10];
    const float* W5 = (const float*)d_in[11]; const float* b5 = (const float*)d_in[12];
    const float* W6 = (const float*)d_in[13]; const float* b6 = (const float*)d_in[14];
    const float* W7 = (const float*)d_in[15]; const float* b7 = (const float*)d_in[16];
    float* out = (float*)d_out;

    int N = in_sizes[0] / 3;
    int n_wtiles = (N + 31) / 32;            // 32-point warp tiles
    int grid = 148 * 2;                      // persistent, 2 CTAs/SM
    int max_grid = (n_wtiles + WARPS - 1) / WARPS;
    if (grid > max_grid) grid = max_grid;

    ngp_mma_kernel<<<grid, THREADS>>>(
        pts, views, tables,
        W1, b1, W2, b2, W3, b3, W4, b4, W5, b5, W6, b6, W7, b7,
        out, N, n_wtiles);
}

// round 14
// speedup vs baseline: 1.0257x; 1.0257x over previous
#include <cuda_runtime.h>
#include <cuda_fp16.h>
#include <cstdint>

// ---------------------------------------------------------------------------
// InstantNGP round 14: R13 with plain (implicit-device) lambdas. R12 base
// (M=32 tile, uint4 frags, interleaved gather) + all-lane SH evaluation +
// permuted W4 input layout (SH dims first -> 4 STS.64 SH staging).
// 256 thr/CTA, 2 CTAs/SM.
// ---------------------------------------------------------------------------

constexpr int THREADS = 256;
constexpr int WARPS = THREADS / 32;
constexpr unsigned TMASK = 524287u;      // T = 2^19 - 1
constexpr float SCALE = 1024.0f;         // density-MLP domain scale (2^10)
constexpr float INV_SCALE = 1.0f / 1024.0f;
constexpr int ST = 36;                   // stage row stride in halves (72B)

__device__ __forceinline__ void mma16816(float d[4], const uint32_t a[4],
                                         uint32_t b0, uint32_t b1) {
    asm volatile("mma.sync.aligned.m16n8k16.row.col.f32.f16.f16.f32 "
        "{%0,%1,%2,%3}, {%4,%5,%6,%7}, {%8,%9}, {%0,%1,%2,%3};"
        : "+f"(d[0]), "+f"(d[1]), "+f"(d[2]), "+f"(d[3])
        : "r"(a[0]), "r"(a[1]), "r"(a[2]), "r"(a[3]), "r"(b0), "r"(b1));
}

__device__ __forceinline__ uint32_t pack_h2(float x, float y) {
    __half2 h = __floats2half2_rn(x, y);
    return *(uint32_t*)&h;
}
__device__ __forceinline__ uint32_t pack_relu(float x, float y) {
    return pack_h2(fmaxf(x, 0.0f), fmaxf(y, 0.0f));
}

// M=32 layer: one uint4 weight load feeds 4 MMAs (2 n-tiles x 2 m-tiles).
template<int KT, int NT>   // NT even
__device__ __forceinline__ void run_layer32(const uint4* __restrict__ F,
                                            const uint32_t A[2][4][4],
                                            float D[2][8][4], int lane) {
    #pragma unroll
    for (int m = 0; m < 2; m++)
        #pragma unroll
        for (int nt = 0; nt < NT; nt++)
            #pragma unroll
            for (int i = 0; i < 4; i++) D[m][nt][i] = 0.0f;
    #pragma unroll
    for (int kt = 0; kt < KT; kt++)
        #pragma unroll
        for (int ntp = 0; ntp < NT / 2; ntp++) {
            uint4 B = F[(kt * (NT / 2) + ntp) * 32 + lane];
            mma16816(D[0][2 * ntp],     A[0][kt], B.x, B.y);
            mma16816(D[1][2 * ntp],     A[1][kt], B.x, B.y);
            mma16816(D[0][2 * ntp + 1], A[0][kt], B.z, B.w);
            mma16816(D[1][2 * ntp + 1], A[1][kt], B.z, B.w);
        }
}

// final 64->3 layer (one n-tile): uint2 frags
__device__ __forceinline__ void run_layer32_n8(const uint2* __restrict__ F,
                                               const uint32_t A[2][4][4],
                                               float D[2][8][4], int lane) {
    #pragma unroll
    for (int m = 0; m < 2; m++)
        #pragma unroll
        for (int i = 0; i < 4; i++) D[m][0][i] = 0.0f;
    #pragma unroll
    for (int kt = 0; kt < 4; kt++) {
        uint2 B = F[kt * 32 + lane];
        mma16816(D[0][0], A[0][kt], B.x, B.y);
        mma16816(D[1][0], A[1][kt], B.x, B.y);
    }
}

// fp32 D (+bias, relu) -> f16 A fragments of next layer, fully in registers.
template<int NT>
__device__ __forceinline__ void convert_relu(const float D[2][8][4],
                                             const float* __restrict__ bias,
                                             uint32_t A[2][4][4], int lane) {
    const int c = (lane & 3) * 2;
    #pragma unroll
    for (int kt = 0; kt < NT / 2; kt++) {
        const int j = 2 * kt;
        float b00 = bias[8 * j + c],     b01 = bias[8 * j + c + 1];
        float b10 = bias[8 * j + 8 + c], b11 = bias[8 * j + 8 + c + 1];
        #pragma unroll
        for (int m = 0; m < 2; m++) {
            A[m][kt][0] = pack_relu(D[m][j][0] + b00,     D[m][j][1] + b01);
            A[m][kt][1] = pack_relu(D[m][j][2] + b00,     D[m][j][3] + b01);
            A[m][kt][2] = pack_relu(D[m][j + 1][0] + b10, D[m][j + 1][1] + b11);
            A[m][kt][3] = pack_relu(D[m][j + 1][2] + b10, D[m][j + 1][3] + b11);
        }
    }
}

// load A fragments (2 m-tiles x 2 k-tiles) from per-warp 32-row stage
__device__ __forceinline__ void load_A2(const __half* __restrict__ st,
                                        uint32_t A[2][4][4], int lane) {
    const int r = lane >> 2, c = (lane & 3) * 2;
    #pragma unroll
    for (int m = 0; m < 2; m++)
        #pragma unroll
        for (int kt = 0; kt < 2; kt++) {
            int row = r + 16 * m, col = c + 16 * kt;
            A[m][kt][0] = *(const uint32_t*)(st + row * ST + col);
            A[m][kt][1] = *(const uint32_t*)(st + (row + 8) * ST + col);
            A[m][kt][2] = *(const uint32_t*)(st + row * ST + col + 8);
            A[m][kt][3] = *(const uint32_t*)(st + (row + 8) * ST + col + 8);
        }
}

// fill vectorized frag groups (NT even). kmap: permuted source row, or -1=zero.
template<typename KMAP>
__device__ __forceinline__ void fill_frags_v4m(uint4* frag, const float* __restrict__ W,
                                               int Nout, int KT, int NT, int tid,
                                               KMAP kmap) {
    const int total = KT * (NT / 2) * 32;
    for (int v = tid; v < total; v += THREADS) {
        int lane = v & 31, g = v >> 5;
        int kt = g / (NT / 2), ntp = g % (NT / 2);
        uint32_t words[4];
        #pragma unroll
        for (int j = 0; j < 4; j++) {
            int nt = ntp * 2 + (j >> 1), reg = j & 1;
            int k = kt * 16 + (lane & 3) * 2 + reg * 8;
            int n = nt * 8 + (lane >> 2);
            int k0 = kmap(k), k1 = kmap(k + 1);
            float w0 = (k0 >= 0 && n < Nout) ? W[k0 * Nout + n] : 0.0f;
            float w1 = (k1 >= 0 && n < Nout) ? W[k1 * Nout + n] : 0.0f;
            words[j] = pack_h2(w0, w1);
        }
        frag[v] = make_uint4(words[0], words[1], words[2], words[3]);
    }
}

__device__ __forceinline__ void fill_frags_v2(uint2* frag, const float* __restrict__ W,
                                              int K, int Nout, int tid) {
    for (int v = tid; v < 4 * 32; v += THREADS) {
        int lane = v & 31, kt = v >> 5;
        uint32_t words[2];
        #pragma unroll
        for (int reg = 0; reg < 2; reg++) {
            int k = kt * 16 + (lane & 3) * 2 + reg * 8;
            int n = lane >> 2;
            float w0 = (k < K && n < Nout) ? W[k * Nout + n] : 0.0f;
            float w1 = (k + 1 < K && n < Nout) ? W[(k + 1) * Nout + n] : 0.0f;
            words[reg] = pack_h2(w0, w1);
        }
        frag[v] = make_uint2(words[0], words[1]);
    }
}

// per-lane corner indices (with level offset) + weights for one level
__device__ __forceinline__ void hash_level(int l, float res, float Px, float Py, float Pz,
                                           int half, unsigned idx[4], float w[4]) {
    float px = Px * res, py = Py * res, pz = Pz * res;
    float fx = floorf(px), fy = floorf(py), fz = floorf(pz);
    float fracx = px - fx;
    float wxh = half ? fracx : (1.0f - fracx);
    float wy1 = py - fy, wy0 = 1.0f - wy1;
    float wz1 = pz - fz, wz0 = 1.0f - wz1;
    unsigned ix = (unsigned)fx, iy = (unsigned)fy, iz = (unsigned)fz;
    unsigned hxh = ix + (unsigned)half;
    unsigned hy0 = iy * 2654435761u, hy1 = (iy + 1u) * 2654435761u;
    unsigned hz0 = iz * 805459861u,  hz1 = (iz + 1u) * 805459861u;
    const unsigned base = (unsigned)l << 19;
    idx[0] = ((hxh ^ hy0 ^ hz0) & TMASK) + base;  w[0] = wxh * wy0 * wz0;
    idx[1] = ((hxh ^ hy0 ^ hz1) & TMASK) + base;  w[1] = wxh * wy0 * wz1;
    idx[2] = ((hxh ^ hy1 ^ hz0) & TMASK) + base;  w[2] = wxh * wy1 * wz0;
    idx[3] = ((hxh ^ hy1 ^ hz1) & TMASK) + base;  w[3] = wxh * wy1 * wz1;
}

__global__ __launch_bounds__(THREADS, 2)
void ngp_mma_kernel(const float* __restrict__ pts,
                    const float* __restrict__ views,
                    const float* __restrict__ tables,
                    const float* __restrict__ W1, const float* __restrict__ b1,
                    const float* __restrict__ W2, const float* __restrict__ b2,
                    const float* __restrict__ W3, const float* __restrict__ b3,
                    const float* __restrict__ W4, const float* __restrict__ b4,
                    const float* __restrict__ W5, const float* __restrict__ b5,
                    const float* __restrict__ W6, const float* __restrict__ b6,
                    const float* __restrict__ W7, const float* __restrict__ b7,
                    float* __restrict__ out, int N, int n_wtiles) {
    __shared__ uint4 sF1[256], sF2[512], sF3[128], sF4[256], sF5[512], sF6[512];
    __shared__ uint2 sF7[128];
    __shared__ float sB1[64], sB2[64], sB3[16], sB4[64], sB5[64], sB6[64], sB7[4];
    __shared__ __half sStage[WARPS][32 * ST];

    const int tid = threadIdx.x;
    // Lambdas inside a __global__ function are implicitly device-callable.
    auto kid = [](int k) { return k; };
    // W4 input permutation: new dims 0..15 = SH (old rows 15..30),
    // new dims 16..30 = x16[1:16] (old rows 0..14), dim 31 = zero.
    auto k4 = [](int k) {
        return (k < 16) ? (15 + k) : ((k < 31) ? (k - 16) : -1);
    };
    auto kclip32 = [](int k) { return k < 32 ? k : -1; };
    fill_frags_v4m(sF1, W1, 64, 2, 8, tid, kclip32);
    fill_frags_v4m(sF2, W2, 64, 4, 8, tid, kid);
    fill_frags_v4m(sF3, W3, 16, 4, 2, tid, kid);
    fill_frags_v4m(sF4, W4, 64, 2, 8, tid, k4);
    fill_frags_v4m(sF5, W5, 64, 4, 8, tid, kid);
    fill_frags_v4m(sF6, W6, 64, 4, 8, tid, kid);
    fill_frags_v2(sF7, W7, 64, 3, tid);
    if (tid < 64) {
        sB1[tid] = b1[tid] * SCALE;
        sB2[tid] = b2[tid] * SCALE;
        sB4[tid] = b4[tid];
        sB5[tid] = b5[tid];
        sB6[tid] = b6[tid];
    }
    if (tid < 16) sB3[tid] = b3[tid] * SCALE;
    if (tid < 4)  sB7[tid] = (tid < 3) ? b7[tid] : 0.0f;
    __syncthreads();

    const int lane = tid & 31, wid = tid >> 5;
    __half* st = sStage[wid];
    const int r = lane >> 2, cbase = (lane & 3) * 2;
    const int pt = lane & 15, half = lane >> 4;

    // level resolutions: 16 * 2^(6l/7) (correctness-proven form)
    float resl[8];
    #pragma unroll
    for (int l = 0; l < 8; l++)
        resl[l] = 16.0f * exp2f((float)l * (6.0f / 7.0f));

    const float4* __restrict__ tabs = (const float4*)tables;

    for (int t = blockIdx.x * WARPS + wid; t < n_wtiles; t += gridDim.x * WARPS) {
        const int p0 = t * 32;

        // ---- interleaved dual-subtile gather: per level, compute indices for
        //      both 16-point halves, issue all 8 LDG.128, then weight both ----
        {
            const int pA = p0 + pt,      pB = p0 + 16 + pt;
            const int ppA = pA < N ? pA : N - 1;
            const int ppB = pB < N ? pB : N - 1;
            const float PAx = pts[3 * ppA], PAy = pts[3 * ppA + 1], PAz = pts[3 * ppA + 2];
            const float PBx = pts[3 * ppB], PBy = pts[3 * ppB + 1], PBz = pts[3 * ppB + 2];

            #pragma unroll 1
            for (int l = 0; l < 8; l++) {
                unsigned iA[4], iB[4];
                float wA[4], wB[4];
                hash_level(l, resl[l], PAx, PAy, PAz, half, iA, wA);
                hash_level(l, resl[l], PBx, PBy, PBz, half, iB, wB);
                float4 fA0 = __ldg(tabs + iA[0]);
                float4 fA1 = __ldg(tabs + iA[1]);
                float4 fA2 = __ldg(tabs + iA[2]);
                float4 fA3 = __ldg(tabs + iA[3]);
                float4 fB0 = __ldg(tabs + iB[0]);
                float4 fB1 = __ldg(tabs + iB[1]);
                float4 fB2 = __ldg(tabs + iB[2]);
                float4 fB3 = __ldg(tabs + iB[3]);

                float a0 = wA[0]*fA0.x + wA[1]*fA1.x + wA[2]*fA2.x + wA[3]*fA3.x;
                float a1 = wA[0]*fA0.y + wA[1]*fA1.y + wA[2]*fA2.y + wA[3]*fA3.y;
                float a2 = wA[0]*fA0.z + wA[1]*fA1.z + wA[2]*fA2.z + wA[3]*fA3.z;
                float a3 = wA[0]*fA0.w + wA[1]*fA1.w + wA[2]*fA2.w + wA[3]*fA3.w;
                a0 += __shfl_xor_sync(0xffffffffu, a0, 16);
                a1 += __shfl_xor_sync(0xffffffffu, a1, 16);
                a2 += __shfl_xor_sync(0xffffffffu, a2, 16);
                a3 += __shfl_xor_sync(0xffffffffu, a3, 16);

                float b0v = wB[0]*fB0.x + wB[1]*fB1.x + wB[2]*fB2.x + wB[3]*fB3.x;
                float b1v = wB[0]*fB0.y + wB[1]*fB1.y + wB[2]*fB2.y + wB[3]*fB3.y;
                float b2v = wB[0]*fB0.z + wB[1]*fB1.z + wB[2]*fB2.z + wB[3]*fB3.z;
                float b3v = wB[0]*fB0.w + wB[1]*fB1.w + wB[2]*fB2.w + wB[3]*fB3.w;
                b0v += __shfl_xor_sync(0xffffffffu, b0v, 16);
                b1v += __shfl_xor_sync(0xffffffffu, b1v, 16);
                b2v += __shfl_xor_sync(0xffffffffu, b2v, 16);
                b3v += __shfl_xor_sync(0xffffffffu, b3v, 16);

                if (half == 0) {
                    uint2 vA = make_uint2(pack_h2(a0 * SCALE, a1 * SCALE),
                                          pack_h2(a2 * SCALE, a3 * SCALE));
                    *(uint2*)(st + pt * ST + 4 * l) = vA;
                    uint2 vB = make_uint2(pack_h2(b0v * SCALE, b1v * SCALE),
                                          pack_h2(b2v * SCALE, b3v * SCALE));
                    *(uint2*)(st + (16 + pt) * ST + 4 * l) = vB;
                }
            }
        }
        __syncwarp();

        uint32_t A[2][4][4];
        float D[2][8][4];

        load_A2(st, A, lane);
        run_layer32<2, 8>(sF1, A, D, lane);
        convert_relu<8>(D, sB1, A, lane);
        run_layer32<4, 8>(sF2, A, D, lane);
        convert_relu<8>(D, sB2, A, lane);
        run_layer32<4, 2>(sF3, A, D, lane);

        // ---------- density out + stage x16[1:16] at cols 16..30 ----------
        __syncwarp();   // all lanes done reading stage (L1 input) before overwrite
        #pragma unroll
        for (int m = 0; m < 2; m++) {
            const int row0 = r + 16 * m;
            if ((lane & 3) == 0) {
                float v0 = (D[m][0][0] + sB3[0]) * INV_SCALE;
                float v2 = (D[m][0][2] + sB3[0]) * INV_SCALE;
                int pt0 = p0 + row0, pt1 = p0 + row0 + 8;
                if (pt0 < N) out[3 * N + pt0] = fmaxf(v0, 0.0f);
                if (pt1 < N) out[3 * N + pt1] = fmaxf(v2, 0.0f);
            }
            #pragma unroll
            for (int nt = 0; nt < 2; nt++) {
                #pragma unroll
                for (int i = 0; i < 2; i++) {
                    int g = 8 * nt + cbase + i;
                    if (g >= 1) {
                        float bb = sB3[g];
                        st[row0 * ST + 15 + g]       = __float2half((D[m][nt][i]     + bb) * INV_SCALE);
                        st[(row0 + 8) * ST + 15 + g] = __float2half((D[m][nt][2 + i] + bb) * INV_SCALE);
                    }
                }
            }
        }

        // ---------- SH(view) -> stage cols 0..15 (all 32 lanes; row = lane) ----
        {
            const int prow = lane;              // 16*half + pt == lane
            const int p = p0 + prow;
            const int pp = p < N ? p : N - 1;
            const float vx = views[3 * pp], vy = views[3 * pp + 1], vz = views[3 * pp + 2];
            float inv = rsqrtf(vx * vx + vy * vy + vz * vz);
            float x = vx * inv, y = vy * inv, z = vz * inv;
            float xx = x * x, yy = y * y, zz = z * z;
            uint32_t s01 = pack_h2(0.28209479177387814f,
                                   -0.48860251190291987f * y);
            uint32_t s23 = pack_h2(0.48860251190291987f * z,
                                   -0.48860251190291987f * x);
            uint32_t s45 = pack_h2(1.0925484305920792f * x * y,
                                   -1.0925484305920792f * y * z);
            uint32_t s67 = pack_h2(0.94617469575755997f * zz - 0.31539156525252005f,
                                   -1.0925484305920792f * x * z);
            uint32_t s89 = pack_h2(0.54627421529603959f * (xx - yy),
                                   -0.59004358992664352f * y * (3.0f * xx - yy));
            uint32_t sab = pack_h2(2.8906114426405538f * x * y * z,
                                   -0.45704579946446572f * y * (4.0f * zz - xx - yy));
            uint32_t scd = pack_h2(0.37317633259011546f * z * (2.0f * zz - 3.0f * xx - 3.0f * yy),
                                   -0.45704579946446572f * x * (4.0f * zz - xx - yy));
            uint32_t sef = pack_h2(1.4453057213202769f * z * (xx - yy),
                                   -0.59004358992664352f * x * (xx - 3.0f * yy));
            __half* row = st + prow * ST;
            *(uint2*)(row + 0)  = make_uint2(s01, s23);
            *(uint2*)(row + 4)  = make_uint2(s45, s67);
            *(uint2*)(row + 8)  = make_uint2(s89, sab);
            *(uint2*)(row + 12) = make_uint2(scd, sef);
            row[31] = __float2half(0.0f);       // padded input dim
        }
        __syncwarp();

        load_A2(st, A, lane);
        run_layer32<2, 8>(sF4, A, D, lane);
        convert_relu<8>(D, sB4, A, lane);
        run_layer32<4, 8>(sF5, A, D, lane);
        convert_relu<8>(D, sB5, A, lane);
        run_layer32<4, 8>(sF6, A, D, lane);
        convert_relu<8>(D, sB6, A, lane);
        run_layer32_n8(sF7, A, D, lane);

        // ---------- sigmoid color out (cols 0..2 of D ntile 0) ----------
        #pragma unroll
        for (int m = 0; m < 2; m++) {
            #pragma unroll
            for (int i = 0; i < 2; i++) {
                int col = cbase + i;
                if (col < 3) {
                    int pt0 = p0 + r + 16 * m, pt1 = pt0 + 8;
                    float o0 = D[m][0][i] + sB7[col];
                    float o1 = D[m][0][2 + i] + sB7[col];
                    if (pt0 < N) out[3 * pt0 + col] = 1.0f / (1.0f + __expf(-o0));
                    if (pt1 < N) out[3 * pt1 + col] = 1.0f / (1.0f + __expf(-o1));
                }
            }
        }
        __syncwarp();  // stage reuse safety for next iteration
    }
}

extern "C" void kernel_launch(void* const* d_in, const int* in_sizes, int n_in,
                              void* d_out, int out_size) {
    const float* pts    = (const float*)d_in[0];
    const float* views  = (const float*)d_in[1];
    const float* tables = (const float*)d_in[2];
    const float* W1 = (const float*)d_in[3];  const float* b1 = (const float*)d_in[4];
    const float* W2 = (const float*)d_in[5];  const float* b2 = (const float*)d_in[6];
    const float* W3 = (const float*)d_in[7];  const float* b3 = (const float*)d_in[8];
    const float* W4 = (const float*)d_in[9];  const float* b4 = (const float*)d_in[10];
    const float* W5 = (const float*)d_in[11]; const float* b5 = (const float*)d_in[12];
    const float* W6 = (const float*)d_in[13]; const float* b6 = (const float*)d_in[14];
    const float* W7 = (const float*)d_in[15]; const float* b7 = (const float*)d_in[16];
    float* out = (float*)d_out;

    int N = in_sizes[0] / 3;
    int n_wtiles = (N + 31) / 32;            // 32-point warp tiles
    int grid = 148 * 2;                      // persistent, 2 CTAs/SM
    int max_grid = (n_wtiles + WARPS - 1) / WARPS;
    if (grid > max_grid) grid = max_grid;

    ngp_mma_kernel<<<grid, THREADS>>>(
        pts, views, tables,
        W1, b1, W2, b2, W3, b3, W4, b4, W5, b5, W6, b6, W7, b7,
        out, N, n_wtiles);
}

// round 16
// speedup vs baseline: 1.0486x; 1.0223x over previous
#include <cuda_runtime.h>
#include <cuda_fp16.h>
#include <cstdint>

// ---------------------------------------------------------------------------
// InstantNGP round 16: R15 with 16B-aligned stage rows (ST=40 halves = 80B)
// so ldmatrix.x4 activation loads are legal. M=32 tile, uint4 weight frags,
// interleaved gather, permuted W4 (SH-first). 256 thr/CTA, 2 CTAs/SM.
// ---------------------------------------------------------------------------

constexpr int THREADS = 256;
constexpr int WARPS = THREADS / 32;
constexpr unsigned TMASK = 524287u;      // T = 2^19 - 1
constexpr float SCALE = 1024.0f;         // density-MLP domain scale (2^10)
constexpr float INV_SCALE = 1.0f / 1024.0f;
constexpr int ST = 40;                   // stage row stride in halves (80B, 16B-aligned)

__device__ __forceinline__ void mma16816(float d[4], const uint32_t a[4],
                                         uint32_t b0, uint32_t b1) {
    asm volatile("mma.sync.aligned.m16n8k16.row.col.f32.f16.f16.f32 "
        "{%0,%1,%2,%3}, {%4,%5,%6,%7}, {%8,%9}, {%0,%1,%2,%3};"
        : "+f"(d[0]), "+f"(d[1]), "+f"(d[2]), "+f"(d[3])
        : "r"(a[0]), "r"(a[1]), "r"(a[2]), "r"(a[3]), "r"(b0), "r"(b1));
}

__device__ __forceinline__ uint32_t pack_h2(float x, float y) {
    __half2 h = __floats2half2_rn(x, y);
    return *(uint32_t*)&h;
}
__device__ __forceinline__ uint32_t pack_relu(float x, float y) {
    return pack_h2(fmaxf(x, 0.0f), fmaxf(y, 0.0f));
}

__device__ __forceinline__ uint32_t smem_u32(const void* p) {
    uint32_t a;
    asm("{ .reg .u64 t; cvta.to.shared.u64 t, %1; cvt.u32.u64 %0, t; }"
        : "=r"(a) : "l"(p));
    return a;
}

__device__ __forceinline__ void ldsm_x4(uint32_t A[4], uint32_t addr) {
    asm volatile("ldmatrix.sync.aligned.m8n8.x4.shared.b16 {%0,%1,%2,%3}, [%4];"
        : "=r"(A[0]), "=r"(A[1]), "=r"(A[2]), "=r"(A[3]) : "r"(addr));
}

// M=32 layer: one uint4 weight load feeds 4 MMAs (2 n-tiles x 2 m-tiles).
template<int KT, int NT>   // NT even
__device__ __forceinline__ void run_layer32(const uint4* __restrict__ F,
                                            const uint32_t A[2][4][4],
                                            float D[2][8][4], int lane) {
    #pragma unroll
    for (int m = 0; m < 2; m++)
        #pragma unroll
        for (int nt = 0; nt < NT; nt++)
            #pragma unroll
            for (int i = 0; i < 4; i++) D[m][nt][i] = 0.0f;
    #pragma unroll
    for (int kt = 0; kt < KT; kt++)
        #pragma unroll
        for (int ntp = 0; ntp < NT / 2; ntp++) {
            uint4 B = F[(kt * (NT / 2) + ntp) * 32 + lane];
            mma16816(D[0][2 * ntp],     A[0][kt], B.x, B.y);
            mma16816(D[1][2 * ntp],     A[1][kt], B.x, B.y);
            mma16816(D[0][2 * ntp + 1], A[0][kt], B.z, B.w);
            mma16816(D[1][2 * ntp + 1], A[1][kt], B.z, B.w);
        }
}

// final 64->3 layer (one n-tile): uint2 frags
__device__ __forceinline__ void run_layer32_n8(const uint2* __restrict__ F,
                                               const uint32_t A[2][4][4],
                                               float D[2][8][4], int lane) {
    #pragma unroll
    for (int m = 0; m < 2; m++)
        #pragma unroll
        for (int i = 0; i < 4; i++) D[m][0][i] = 0.0f;
    #pragma unroll
    for (int kt = 0; kt < 4; kt++) {
        uint2 B = F[kt * 32 + lane];
        mma16816(D[0][0], A[0][kt], B.x, B.y);
        mma16816(D[1][0], A[1][kt], B.x, B.y);
    }
}

// fp32 D (+bias, relu) -> f16 A fragments of next layer, fully in registers.
template<int NT>
__device__ __forceinline__ void convert_relu(const float D[2][8][4],
                                             const float* __restrict__ bias,
                                             uint32_t A[2][4][4], int lane) {
    const int c = (lane & 3) * 2;
    #pragma unroll
    for (int kt = 0; kt < NT / 2; kt++) {
        const int j = 2 * kt;
        float b00 = bias[8 * j + c],     b01 = bias[8 * j + c + 1];
        float b10 = bias[8 * j + 8 + c], b11 = bias[8 * j + 8 + c + 1];
        #pragma unroll
        for (int m = 0; m < 2; m++) {
            A[m][kt][0] = pack_relu(D[m][j][0] + b00,     D[m][j][1] + b01);
            A[m][kt][1] = pack_relu(D[m][j][2] + b00,     D[m][j][3] + b01);
            A[m][kt][2] = pack_relu(D[m][j + 1][0] + b10, D[m][j + 1][1] + b11);
            A[m][kt][3] = pack_relu(D[m][j + 1][2] + b10, D[m][j + 1][3] + b11);
        }
    }
}

// load A fragments (2 m-tiles x 2 k-tiles) via ldmatrix.x4.
// Per x4: lanes 0-7 -> quad a0 rows, 8-15 -> a1, 16-23 -> a2, 24-31 -> a3.
// Address row = lane & 15, col = kt*16 + (lane>>4)*8.
__device__ __forceinline__ void load_A2m(uint32_t stbase, uint32_t A[2][4][4], int lane) {
    const int row = lane & 15;
    const int coff = (lane >> 4) * 8;
    #pragma unroll
    for (int m = 0; m < 2; m++)
        #pragma unroll
        for (int kt = 0; kt < 2; kt++) {
            uint32_t addr = stbase + (uint32_t)(((row + 16 * m) * ST + kt * 16 + coff) * 2);
            ldsm_x4(A[m][kt], addr);
        }
}

// fill vectorized frag groups (NT even). kmap: permuted source row, or -1=zero.
template<typename KMAP>
__device__ __forceinline__ void fill_frags_v4m(uint4* frag, const float* __restrict__ W,
                                               int Nout, int KT, int NT, int tid,
                                               KMAP kmap) {
    const int total = KT * (NT / 2) * 32;
    for (int v = tid; v < total; v += THREADS) {
        int lane = v & 31, g = v >> 5;
        int kt = g / (NT / 2), ntp = g % (NT / 2);
        uint32_t words[4];
        #pragma unroll
        for (int j = 0; j < 4; j++) {
            int nt = ntp * 2 + (j >> 1), reg = j & 1;
            int k = kt * 16 + (lane & 3) * 2 + reg * 8;
            int n = nt * 8 + (lane >> 2);
            int k0 = kmap(k), k1 = kmap(k + 1);
            float w0 = (k0 >= 0 && n < Nout) ? W[k0 * Nout + n] : 0.0f;
            float w1 = (k1 >= 0 && n < Nout) ? W[k1 * Nout + n] : 0.0f;
            words[j] = pack_h2(w0, w1);
        }
        frag[v] = make_uint4(words[0], words[1], words[2], words[3]);
    }
}

__device__ __forceinline__ void fill_frags_v2(uint2* frag, const float* __restrict__ W,
                                              int K, int Nout, int tid) {
    for (int v = tid; v < 4 * 32; v += THREADS) {
        int lane = v & 31, kt = v >> 5;
        uint32_t words[2];
        #pragma unroll
        for (int reg = 0; reg < 2; reg++) {
            int k = kt * 16 + (lane & 3) * 2 + reg * 8;
            int n = lane >> 2;
            float w0 = (k < K && n < Nout) ? W[k * Nout + n] : 0.0f;
            float w1 = (k + 1 < K && n < Nout) ? W[(k + 1) * Nout + n] : 0.0f;
            words[reg] = pack_h2(w0, w1);
        }
        frag[v] = make_uint2(words[0], words[1]);
    }
}

// per-lane corner indices (with level offset) + weights for one level
__device__ __forceinline__ void hash_level(int l, float res, float Px, float Py, float Pz,
                                           int half, unsigned idx[4], float w[4]) {
    float px = Px * res, py = Py * res, pz = Pz * res;
    float fx = floorf(px), fy = floorf(py), fz = floorf(pz);
    float fracx = px - fx;
    float wxh = half ? fracx : (1.0f - fracx);
    float wy1 = py - fy, wy0 = 1.0f - wy1;
    float wz1 = pz - fz, wz0 = 1.0f - wz1;
    unsigned ix = (unsigned)fx, iy = (unsigned)fy, iz = (unsigned)fz;
    unsigned hxh = ix + (unsigned)half;
    unsigned hy0 = iy * 2654435761u, hy1 = (iy + 1u) * 2654435761u;
    unsigned hz0 = iz * 805459861u,  hz1 = (iz + 1u) * 805459861u;
    const unsigned base = (unsigned)l << 19;
    idx[0] = ((hxh ^ hy0 ^ hz0) & TMASK) + base;  w[0] = wxh * wy0 * wz0;
    idx[1] = ((hxh ^ hy0 ^ hz1) & TMASK) + base;  w[1] = wxh * wy0 * wz1;
    idx[2] = ((hxh ^ hy1 ^ hz0) & TMASK) + base;  w[2] = wxh * wy1 * wz0;
    idx[3] = ((hxh ^ hy1 ^ hz1) & TMASK) + base;  w[3] = wxh * wy1 * wz1;
}

__global__ __launch_bounds__(THREADS, 2)
void ngp_mma_kernel(const float* __restrict__ pts,
                    const float* __restrict__ views,
                    const float* __restrict__ tables,
                    const float* __restrict__ W1, const float* __restrict__ b1,
                    const float* __restrict__ W2, const float* __restrict__ b2,
                    const float* __restrict__ W3, const float* __restrict__ b3,
                    const float* __restrict__ W4, const float* __restrict__ b4,
                    const float* __restrict__ W5, const float* __restrict__ b5,
                    const float* __restrict__ W6, const float* __restrict__ b6,
                    const float* __restrict__ W7, const float* __restrict__ b7,
                    float* __restrict__ out, int N, int n_wtiles) {
    __shared__ uint4 sF1[256], sF2[512], sF3[128], sF4[256], sF5[512], sF6[512];
    __shared__ uint2 sF7[128];
    __shared__ float sB1[64], sB2[64], sB3[16], sB4[64], sB5[64], sB6[64], sB7[4];
    __shared__ __half sStage[WARPS][32 * ST];

    const int tid = threadIdx.x;
    auto kid = [](int k) { return k; };
    // W4 input permutation: new dims 0..15 = SH (old rows 15..30),
    // new dims 16..30 = x16[1:16] (old rows 0..14), dim 31 = zero.
    auto k4 = [](int k) {
        return (k < 16) ? (15 + k) : ((k < 31) ? (k - 16) : -1);
    };
    auto kclip32 = [](int k) { return k < 32 ? k : -1; };
    fill_frags_v4m(sF1, W1, 64, 2, 8, tid, kclip32);
    fill_frags_v4m(sF2, W2, 64, 4, 8, tid, kid);
    fill_frags_v4m(sF3, W3, 16, 4, 2, tid, kid);
    fill_frags_v4m(sF4, W4, 64, 2, 8, tid, k4);
    fill_frags_v4m(sF5, W5, 64, 4, 8, tid, kid);
    fill_frags_v4m(sF6, W6, 64, 4, 8, tid, kid);
    fill_frags_v2(sF7, W7, 64, 3, tid);
    if (tid < 64) {
        sB1[tid] = b1[tid] * SCALE;
        sB2[tid] = b2[tid] * SCALE;
        sB4[tid] = b4[tid];
        sB5[tid] = b5[tid];
        sB6[tid] = b6[tid];
    }
    if (tid < 16) sB3[tid] = b3[tid] * SCALE;
    if (tid < 4)  sB7[tid] = (tid < 3) ? b7[tid] : 0.0f;
    __syncthreads();

    const int lane = tid & 31, wid = tid >> 5;
    __half* st = sStage[wid];
    const uint32_t stb = smem_u32(st);
    const int r = lane >> 2, cbase = (lane & 3) * 2;
    const int pt = lane & 15, half = lane >> 4;

    // level resolutions: 16 * 2^(6l/7) (correctness-proven form)
    float resl[8];
    #pragma unroll
    for (int l = 0; l < 8; l++)
        resl[l] = 16.0f * exp2f((float)l * (6.0f / 7.0f));

    const float4* __restrict__ tabs = (const float4*)tables;

    for (int t = blockIdx.x * WARPS + wid; t < n_wtiles; t += gridDim.x * WARPS) {
        const int p0 = t * 32;

        // ---- interleaved dual-subtile gather: per level, compute indices for
        //      both 16-point halves, issue all 8 LDG.128, then weight both ----
        {
            const int pA = p0 + pt,      pB = p0 + 16 + pt;
            const int ppA = pA < N ? pA : N - 1;
            const int ppB = pB < N ? pB : N - 1;
            const float PAx = pts[3 * ppA], PAy = pts[3 * ppA + 1], PAz = pts[3 * ppA + 2];
            const float PBx = pts[3 * ppB], PBy = pts[3 * ppB + 1], PBz = pts[3 * ppB + 2];

            #pragma unroll 1
            for (int l = 0; l < 8; l++) {
                unsigned iA[4], iB[4];
                float wA[4], wB[4];
                hash_level(l, resl[l], PAx, PAy, PAz, half, iA, wA);
                hash_level(l, resl[l], PBx, PBy, PBz, half, iB, wB);
                float4 fA0 = __ldg(tabs + iA[0]);
                float4 fA1 = __ldg(tabs + iA[1]);
                float4 fA2 = __ldg(tabs + iA[2]);
                float4 fA3 = __ldg(tabs + iA[3]);
                float4 fB0 = __ldg(tabs + iB[0]);
                float4 fB1 = __ldg(tabs + iB[1]);
                float4 fB2 = __ldg(tabs + iB[2]);
                float4 fB3 = __ldg(tabs + iB[3]);

                float a0 = wA[0]*fA0.x + wA[1]*fA1.x + wA[2]*fA2.x + wA[3]*fA3.x;
                float a1 = wA[0]*fA0.y + wA[1]*fA1.y + wA[2]*fA2.y + wA[3]*fA3.y;
                float a2 = wA[0]*fA0.z + wA[1]*fA1.z + wA[2]*fA2.z + wA[3]*fA3.z;
                float a3 = wA[0]*fA0.w + wA[1]*fA1.w + wA[2]*fA2.w + wA[3]*fA3.w;
                a0 += __shfl_xor_sync(0xffffffffu, a0, 16);
                a1 += __shfl_xor_sync(0xffffffffu, a1, 16);
                a2 += __shfl_xor_sync(0xffffffffu, a2, 16);
                a3 += __shfl_xor_sync(0xffffffffu, a3, 16);

                float b0v = wB[0]*fB0.x + wB[1]*fB1.x + wB[2]*fB2.x + wB[3]*fB3.x;
                float b1v = wB[0]*fB0.y + wB[1]*fB1.y + wB[2]*fB2.y + wB[3]*fB3.y;
                float b2v = wB[0]*fB0.z + wB[1]*fB1.z + wB[2]*fB2.z + wB[3]*fB3.z;
                float b3v = wB[0]*fB0.w + wB[1]*fB1.w + wB[2]*fB2.w + wB[3]*fB3.w;
                b0v += __shfl_xor_sync(0xffffffffu, b0v, 16);
                b1v += __shfl_xor_sync(0xffffffffu, b1v, 16);
                b2v += __shfl_xor_sync(0xffffffffu, b2v, 16);
                b3v += __shfl_xor_sync(0xffffffffu, b3v, 16);

                if (half == 0) {
                    uint2 vA = make_uint2(pack_h2(a0 * SCALE, a1 * SCALE),
                                          pack_h2(a2 * SCALE, a3 * SCALE));
                    *(uint2*)(st + pt * ST + 4 * l) = vA;
                    uint2 vB = make_uint2(pack_h2(b0v * SCALE, b1v * SCALE),
                                          pack_h2(b2v * SCALE, b3v * SCALE));
                    *(uint2*)(st + (16 + pt) * ST + 4 * l) = vB;
                }
            }
        }
        __syncwarp();

        uint32_t A[2][4][4];
        float D[2][8][4];

        load_A2m(stb, A, lane);
        run_layer32<2, 8>(sF1, A, D, lane);
        convert_relu<8>(D, sB1, A, lane);
        run_layer32<4, 8>(sF2, A, D, lane);
        convert_relu<8>(D, sB2, A, lane);
        run_layer32<4, 2>(sF3, A, D, lane);

        // ---------- density out + stage x16[1:16] at cols 16..30 ----------
        __syncwarp();   // all lanes done reading stage (L1 input) before overwrite
        #pragma unroll
        for (int m = 0; m < 2; m++) {
            const int row0 = r + 16 * m;
            if ((lane & 3) == 0) {
                float v0 = (D[m][0][0] + sB3[0]) * INV_SCALE;
                float v2 = (D[m][0][2] + sB3[0]) * INV_SCALE;
                int pt0 = p0 + row0, pt1 = p0 + row0 + 8;
                if (pt0 < N) out[3 * N + pt0] = fmaxf(v0, 0.0f);
                if (pt1 < N) out[3 * N + pt1] = fmaxf(v2, 0.0f);
            }
            #pragma unroll
            for (int nt = 0; nt < 2; nt++) {
                #pragma unroll
                for (int i = 0; i < 2; i++) {
                    int g = 8 * nt + cbase + i;
                    if (g >= 1) {
                        float bb = sB3[g];
                        st[row0 * ST + 15 + g]       = __float2half((D[m][nt][i]     + bb) * INV_SCALE);
                        st[(row0 + 8) * ST + 15 + g] = __float2half((D[m][nt][2 + i] + bb) * INV_SCALE);
                    }
                }
            }
        }

        // ---------- SH(view) -> stage cols 0..15 (all 32 lanes; row = lane) ----
        {
            const int prow = lane;              // 16*half + pt == lane
            const int p = p0 + prow;
            const int pp = p < N ? p : N - 1;
            const float vx = views[3 * pp], vy = views[3 * pp + 1], vz = views[3 * pp + 2];
            float inv = rsqrtf(vx * vx + vy * vy + vz * vz);
            float x = vx * inv, y = vy * inv, z = vz * inv;
            float xx = x * x, yy = y * y, zz = z * z;
            uint32_t s01 = pack_h2(0.28209479177387814f,
                                   -0.48860251190291987f * y);
            uint32_t s23 = pack_h2(0.48860251190291987f * z,
                                   -0.48860251190291987f * x);
            uint32_t s45 = pack_h2(1.0925484305920792f * x * y,
                                   -1.0925484305920792f * y * z);
            uint32_t s67 = pack_h2(0.94617469575755997f * zz - 0.31539156525252005f,
                                   -1.0925484305920792f * x * z);
            uint32_t s89 = pack_h2(0.54627421529603959f * (xx - yy),
                                   -0.59004358992664352f * y * (3.0f * xx - yy));
            uint32_t sab = pack_h2(2.8906114426405538f * x * y * z,
                                   -0.45704579946446572f * y * (4.0f * zz - xx - yy));
            uint32_t scd = pack_h2(0.37317633259011546f * z * (2.0f * zz - 3.0f * xx - 3.0f * yy),
                                   -0.45704579946446572f * x * (4.0f * zz - xx - yy));
            uint32_t sef = pack_h2(1.4453057213202769f * z * (xx - yy),
                                   -0.59004358992664352f * x * (xx - 3.0f * yy));
            __half* row = st + prow * ST;
            *(uint2*)(row + 0)  = make_uint2(s01, s23);
            *(uint2*)(row + 4)  = make_uint2(s45, s67);
            *(uint2*)(row + 8)  = make_uint2(s89, sab);
            *(uint2*)(row + 12) = make_uint2(scd, sef);
            row[31] = __float2half(0.0f);       // padded input dim
        }
        __syncwarp();

        load_A2m(stb, A, lane);
        run_layer32<2, 8>(sF4, A, D, lane);
        convert_relu<8>(D, sB4, A, lane);
        run_layer32<4, 8>(sF5, A, D, lane);
        convert_relu<8>(D, sB5, A, lane);
        run_layer32<4, 8>(sF6, A, D, lane);
        convert_relu<8>(D, sB6, A, lane);
        run_layer32_n8(sF7, A, D, lane);

        // ---------- sigmoid color out (cols 0..2 of D ntile 0) ----------
        #pragma unroll
        for (int m = 0; m < 2; m++) {
            #pragma unroll
            for (int i = 0; i < 2; i++) {
                int col = cbase + i;
                if (col < 3) {
                    int pt0 = p0 + r + 16 * m, pt1 = pt0 + 8;
                    float o0 = D[m][0][i] + sB7[col];
                    float o1 = D[m][0][2 + i] + sB7[col];
                    if (pt0 < N) out[3 * pt0 + col] = 1.0f / (1.0f + __expf(-o0));
                    if (pt1 < N) out[3 * pt1 + col] = 1.0f / (1.0f + __expf(-o1));
                }
            }
        }
        __syncwarp();  // stage reuse safety for next iteration
    }
}

extern "C" void kernel_launch(void* const* d_in, const int* in_sizes, int n_in,
                              void* d_out, int out_size) {
    const float* pts    = (const float*)d_in[0];
    const float* views  = (const float*)d_in[1];
    const float* tables = (const float*)d_in[2];
    const float* W1 = (const float*)d_in[3];  const float* b1 = (const float*)d_in[4];
    const float* W2 = (const float*)d_in[5];  const float* b2 = (const float*)d_in[6];
    const float* W3 = (const float*)d_in[7];  const float* b3 = (const float*)d_in[8];
    const float* W4 = (const float*)d_in[9];  const float* b4 = (const float*)d_in[10];
    const float* W5 = (const float*)d_in[11]; const float* b5 = (const float*)d_in[12];
    const float* W6 = (const float*)d_in[13]; const float* b6 = (const float*)d_in[14];
    const float* W7 = (const float*)d_in[15]; const float* b7 = (const float*)d_in[16];
    float* out = (float*)d_out;

    int N = in_sizes[0] / 3;
    int n_wtiles = (N + 31) / 32;            // 32-point warp tiles
    int grid = 148 * 2;                      // persistent, 2 CTAs/SM
    int max_grid = (n_wtiles + WARPS - 1) / WARPS;
    if (grid > max_grid) grid = max_grid;

    ngp_mma_kernel<<<grid, THREADS>>>(
        pts, views, tables,
        W1, b1, W2, b2, W3, b3, W4, b4, W5, b5, W6, b6, W7, b7,
        out, N, n_wtiles);
}